// round 3
// baseline (speedup 1.0000x reference)
#include <cuda_runtime.h>
#include <math.h>

#define NB 8
#define NA 512
#define NN 64
#define ND 128
#define NF 128
#define NG 25
#define NL 3
#define NGA 512
#define BA (NB*NA)          // 4096
#define CUTOFF 5.0f
#define RSTART 1.2f
#define LN2F 0.6931471805599453f

// -------- device scratch (static, no allocations) --------
__device__ float d_x[BA*ND];          // current features
__device__ float d_y[BA*NF];          // in2f projection
__device__ float d_agg[BA*NF];        // neighbor-aggregated features
__device__ float d_vang[BA*ND];       // angular term for current layer
__device__ float d_fij[BA*NN*NG];     // gaussian-smeared distances
__device__ float d_cm[BA*NN];         // cutoff * neighbor_mask

__device__ __forceinline__ float ssp(float v) {
    // softplus(v) - ln2, numerically stable
    return fmaxf(v, 0.f) + log1pf(expf(-fabsf(v))) - LN2F;
}

// -------- embedding gather --------
__global__ void embed_kernel(const int* __restrict__ z, const float* __restrict__ emb) {
    int i = blockIdx.x, t = threadIdx.x;
    d_x[i*ND + t] = emb[z[i]*ND + t];
}

// -------- distances + gaussian smearing + cutoff*mask --------
__global__ void dist_kernel(const float* __restrict__ pos,
                            const int* __restrict__ nb,
                            const int* __restrict__ nmask) {
    int i = blockIdx.x;           // atom (global)
    int n = threadIdx.x;          // neighbor
    int bofs = (i >> 9) << 9;     // structure base atom index
    float px = pos[i*3+0], py = pos[i*3+1], pz = pos[i*3+2];
    int j = nb[i*NN + n];
    int gj = bofs + j;
    float dx = pos[gj*3+0] - px;
    float dy = pos[gj*3+1] - py;
    float dz = pos[gj*3+2] - pz;
    float r = sqrtf(dx*dx + dy*dy + dz*dz + 1e-12f);
    float m = (float)nmask[i*NN + n];
    d_cm[i*NN + n] = (r <= CUTOFF) ? m : 0.f;
    const float width = (CUTOFF - RSTART) / (float)(NG - 1);
    const float coeff = -0.5f / (width * width);
    float* out = d_fij + (size_t)(i*NN + n) * NG;
    #pragma unroll
    for (int g = 0; g < NG; g++) {
        float d = r - (RSTART + width * (float)g);
        out[g] = expf(coeff * d * d);
    }
}

// -------- simple tiled GEMM: C[M,128] = A[M,K] @ B[K,128] --------
// amode: 0 -> A = Aext, 1 -> A = d_x
// cmode: 0 -> C = d_y,  1 -> C = d_vang
__global__ __launch_bounds__(128)
void gemm16_kernel(const float* __restrict__ Aext, const float* __restrict__ Bm,
                   int K, int amode, int cmode) {
    __shared__ float Ash[16][32];
    __shared__ float Bsh[32][128];
    const float* Am = (amode == 1) ? d_x : Aext;
    float* Cm = (cmode == 1) ? d_vang : d_y;
    int t = threadIdx.x;
    int row0 = blockIdx.x * 16;
    float acc[16];
    #pragma unroll
    for (int r = 0; r < 16; r++) acc[r] = 0.f;
    for (int kt = 0; kt < K; kt += 32) {
        #pragma unroll
        for (int p = 0; p < 4; p++) {
            int idx = t + 128*p;
            int r = idx >> 5, k = idx & 31;
            Ash[r][k] = Am[(size_t)(row0 + r) * K + kt + k];
        }
        #pragma unroll 8
        for (int kk = 0; kk < 32; kk++)
            Bsh[kk][t] = Bm[(size_t)(kt + kk) * 128 + t];
        __syncthreads();
        #pragma unroll
        for (int kk = 0; kk < 32; kk++) {
            float bv = Bsh[kk][t];
            #pragma unroll
            for (int r = 0; r < 16; r++) acc[r] += Ash[r][kk] * bv;
        }
        __syncthreads();
    }
    #pragma unroll
    for (int r = 0; r < 16; r++)
        Cm[(size_t)(row0 + r) * 128 + t] = acc[r];
}

// -------- fused filter-network + neighbor aggregation --------
// One block handles 2 atoms (i0, i0+1). 256 threads.
// SMEM layout (floats):
//  w2s:   [0,16384)        filt_w2[l]  (k-major: w2s[k*128+f])
//  w1s:   [16384,19584)    filt_w1[l]  (g-major: w1s[g*128+k])
//  Hs:    [19584,35968)    H[a][k][n]  (k-major rows of 64, float4-aligned)
//  fms:   [35968,39168)    f_ij for 2 atoms
//  b1s:   [39168,39296)
//  b2s:   [39296,39424)
//  cms:   [39424,39552)    2*64
//  nbrs:  [39552,39680)    2*64 (int)
#define FA_SMEM_FLOATS 39680

__global__ __launch_bounds__(256)
void filter_agg_kernel(const float* __restrict__ w1, const float* __restrict__ b1,
                       const float* __restrict__ w2, const float* __restrict__ b2,
                       const int* __restrict__ nb, int l) {
    extern __shared__ float sm[];
    float* w2s = sm;
    float* w1s = sm + 16384;
    float* Hs  = sm + 19584;
    float* fms = sm + 35968;
    float* b1s = sm + 39168;
    float* b2s = sm + 39296;
    float* cms = sm + 39424;
    int*   nbrs = (int*)(sm + 39552);

    int t = threadIdx.x;
    int i0 = blockIdx.x * 2;
    int bofs = (i0 >> 9) << 9;

    // ---- stage 0: loads ----
    const float* w2g = w2 + (size_t)l * 16384;
    for (int idx = t; idx < 16384; idx += 256) w2s[idx] = w2g[idx];
    const float* w1g = w1 + (size_t)l * 3200;
    for (int idx = t; idx < 3200; idx += 256) w1s[idx] = w1g[idx];
    const float* fg = d_fij + (size_t)i0 * 1600;
    for (int idx = t; idx < 3200; idx += 256) fms[idx] = fg[idx];
    if (t < 128) {
        b1s[t] = b1[l*128 + t];
        b2s[t] = b2[l*128 + t];
        cms[t] = d_cm[i0*64 + t];
        nbrs[t] = nb[i0*64 + t];
    }
    __syncthreads();

    // ---- stage A: H[a][k][n] = ssp(f_ij @ w1 + b1) ----
    {
        int lane = t & 31;
        int w = t >> 5;           // warp 0..7
        int a = w >> 2;           // atom within block
        int kb = (w & 3) * 32;
        const float* fm = fms + a * 1600;
        float* Ha = Hs + a * 8192;
        // hold this thread's gaussian features in registers
        float f0[NG], f1[NG];
        #pragma unroll
        for (int g = 0; g < NG; g++) {
            f0[g] = fm[lane*NG + g];
            f1[g] = fm[(lane+32)*NG + g];
        }
        for (int k = kb; k < kb + 32; k++) {
            float a0 = b1s[k], a1 = b1s[k];
            #pragma unroll
            for (int g = 0; g < NG; g++) {
                float wv = w1s[g*128 + k];   // warp-uniform broadcast
                a0 += f0[g] * wv;
                a1 += f1[g] * wv;
            }
            Ha[k*64 + lane]      = ssp(a0);
            Ha[k*64 + lane + 32] = ssp(a1);
        }
    }
    __syncthreads();

    // ---- stage B: agg[f] = sum_n cm[n] * y[nbr[n]][f] * (H[n]@w2[:,f] + b2[f]) ----
    {
        int f = t & 127;
        int a = t >> 7;           // atom within block
        const float* Ha = Hs + a * 8192;
        const float* cma = cms + a * 64;
        const int*   nba = nbrs + a * 64;
        const float* yb = d_y + (size_t)bofs * 128;
        float b2f = b2s[f];
        float accf = 0.f;
        for (int n0 = 0; n0 < 64; n0 += 8) {
            float aw[8];
            #pragma unroll
            for (int j = 0; j < 8; j++) aw[j] = b2f;
            #pragma unroll 4
            for (int k = 0; k < 128; k++) {
                float w2v = w2s[k*128 + f];
                float4 h4a = *(const float4*)&Ha[k*64 + n0];      // broadcast
                float4 h4b = *(const float4*)&Ha[k*64 + n0 + 4];  // broadcast
                aw[0] += h4a.x * w2v; aw[1] += h4a.y * w2v;
                aw[2] += h4a.z * w2v; aw[3] += h4a.w * w2v;
                aw[4] += h4b.x * w2v; aw[5] += h4b.y * w2v;
                aw[6] += h4b.z * w2v; aw[7] += h4b.w * w2v;
            }
            #pragma unroll
            for (int j = 0; j < 8; j++) {
                int n = n0 + j;
                accf += cma[n] * yb[(size_t)nba[n]*128 + f] * aw[j];
            }
        }
        d_agg[(size_t)(i0 + a)*128 + f] = accf;
    }
}

// -------- fused epilogue: v_rad = (agg@f2out + b)@dense + b; x += ssp(v_rad + v_ang) --------
__global__ __launch_bounds__(128)
void out_kernel(const float* __restrict__ f2w, const float* __restrict__ f2b,
                const float* __restrict__ dw, const float* __restrict__ db, int l) {
    __shared__ float aggs[128];
    __shared__ float ts[128];
    int t = threadIdx.x;
    int i = blockIdx.x;
    aggs[t] = d_agg[(size_t)i*128 + t];
    __syncthreads();
    const float* wA = f2w + (size_t)l * 16384;
    float acc = f2b[l*128 + t];
    #pragma unroll 4
    for (int k = 0; k < 128; k++) acc += aggs[k] * wA[k*128 + t];
    ts[t] = acc;
    __syncthreads();
    const float* wB = dw + (size_t)l * 16384;
    float acc2 = db[l*128 + t];
    #pragma unroll 4
    for (int k = 0; k < 128; k++) acc2 += ts[k] * wB[k*128 + t];
    float v = acc2 + d_vang[(size_t)i*128 + t];
    d_x[(size_t)i*128 + t] += ssp(v);
}

__global__ void copy_out_kernel(float* __restrict__ out) {
    int idx = blockIdx.x * 256 + threadIdx.x;
    out[idx] = d_x[idx];
}

extern "C" void kernel_launch(void* const* d_in, const int* in_sizes, int n_in,
                              void* d_out, int out_size) {
    const int*   z      = (const int*)  d_in[0];   // atomic_numbers [B,A]
    const float* pos    = (const float*)d_in[1];   // positions [B,A,3]
    const int*   nb     = (const int*)  d_in[2];   // neighbors [B,A,N]
    const int*   nmask  = (const int*)  d_in[3];   // neighbor_mask [B,A,N]
    const float* Gi     = (const float*)d_in[4];   // G_i [B,A,GA]
    const float* emb    = (const float*)d_in[5];   // embedding [100,D]
    const float* fw1    = (const float*)d_in[6];   // filt_w1 [L,G,F]
    const float* fb1    = (const float*)d_in[7];   // filt_b1 [L,F]
    const float* fw2    = (const float*)d_in[8];   // filt_w2 [L,F,F]
    const float* fb2    = (const float*)d_in[9];   // filt_b2 [L,F]
    const float* in2f   = (const float*)d_in[10];  // in2f_w [L,D,F]
    const float* f2o    = (const float*)d_in[11];  // f2out_w [L,F,D]
    const float* f2ob   = (const float*)d_in[12];  // f2out_b [L,D]
    const float* dw     = (const float*)d_in[13];  // dense_w [L,D,D]
    const float* db     = (const float*)d_in[14];  // dense_b [L,D]
    const float* angw   = (const float*)d_in[15];  // ang_w [L,GA,D]
    float* out = (float*)d_out;

    cudaFuncSetAttribute(filter_agg_kernel,
                         cudaFuncAttributeMaxDynamicSharedMemorySize,
                         FA_SMEM_FLOATS * 4);

    embed_kernel<<<BA, 128>>>(z, emb);
    dist_kernel<<<BA, NN>>>(pos, nb, nmask);

    for (int l = 0; l < NL; l++) {
        // y = x @ in2f_w[l]   (A = d_x, C = d_y)
        gemm16_kernel<<<BA/16, 128>>>(nullptr, in2f + (size_t)l*ND*NF, ND, 1, 0);
        // filter network + neighbor aggregation
        filter_agg_kernel<<<BA/2, 256, FA_SMEM_FLOATS*4>>>(fw1, fb1, fw2, fb2, nb, l);
        // v_ang = G_i @ ang_w[l]   (A = Gi, C = d_vang)
        gemm16_kernel<<<BA/16, 128>>>(Gi, angw + (size_t)l*NGA*ND, NGA, 0, 1);
        // epilogue: two dense layers + residual ssp update
        out_kernel<<<BA, 128>>>(f2o, f2ob, dw, db, l);
    }

    copy_out_kernel<<<BA*ND/256, 256>>>(out);
}

// round 5
// speedup vs baseline: 1.3730x; 1.3730x over previous
#include <cuda_runtime.h>
#include <math.h>

#define NB 8
#define NA 512
#define NN 64
#define ND 128
#define NF 128
#define NG 25
#define NL 3
#define NGA 512
#define BA (NB*NA)          // 4096
#define CUTOFF 5.0f
#define RSTART 1.2f
#define LN2F 0.6931471805599453f

// -------- device scratch (static, no allocations) --------
__device__ float d_x[BA*ND];          // current features
__device__ float d_y[BA*NF];          // in2f projection
__device__ float d_agg[BA*NF];        // neighbor-aggregated features
__device__ float d_vang[NL*BA*ND];    // angular terms (all layers, precomputed)
__device__ float d_fij[BA*NN*NG];     // gaussian-smeared distances
__device__ float d_cm[BA*NN];         // cutoff * neighbor_mask

__device__ __forceinline__ float ssp(float v) {
    return fmaxf(v, 0.f) + log1pf(expf(-fabsf(v))) - LN2F;
}

// -------- embedding gather --------
__global__ void embed_kernel(const int* __restrict__ z, const float* __restrict__ emb) {
    int i = blockIdx.x, t = threadIdx.x;
    d_x[i*ND + t] = emb[z[i]*ND + t];
}

// -------- distances + gaussian smearing + cutoff*mask --------
__global__ void dist_kernel(const float* __restrict__ pos,
                            const int* __restrict__ nb,
                            const int* __restrict__ nmask) {
    int i = blockIdx.x;
    int n = threadIdx.x;
    int bofs = (i >> 9) << 9;
    float px = pos[i*3+0], py = pos[i*3+1], pz = pos[i*3+2];
    int j = nb[i*NN + n];
    int gj = bofs + j;
    float dx = pos[gj*3+0] - px;
    float dy = pos[gj*3+1] - py;
    float dz = pos[gj*3+2] - pz;
    float r = sqrtf(dx*dx + dy*dy + dz*dz + 1e-12f);
    float m = (float)nmask[i*NN + n];
    d_cm[i*NN + n] = (r <= CUTOFF) ? m : 0.f;
    const float width = (CUTOFF - RSTART) / (float)(NG - 1);
    const float coeff = -0.5f / (width * width);
    float* out = d_fij + (size_t)(i*NN + n) * NG;
    #pragma unroll
    for (int g = 0; g < NG; g++) {
        float d = r - (RSTART + width * (float)g);
        out[g] = expf(coeff * d * d);
    }
}

// -------- simple tiled GEMM: C[M,128] = A[M,K] @ B[K,128] --------
// amode: 0 -> A = Aext, 1 -> A = d_x
// cmode: 0 -> C = d_y,  1 -> C = d_vang + cofs
__global__ __launch_bounds__(128)
void gemm16_kernel(const float* __restrict__ Aext, const float* __restrict__ Bm,
                   int K, int amode, int cmode, int cofs) {
    __shared__ float Ash[16][32];
    __shared__ float Bsh[32][128];
    const float* Am = (amode == 1) ? d_x : Aext;
    float* Cm = (cmode == 1) ? (d_vang + cofs) : d_y;
    int t = threadIdx.x;
    int row0 = blockIdx.x * 16;
    float acc[16];
    #pragma unroll
    for (int r = 0; r < 16; r++) acc[r] = 0.f;
    for (int kt = 0; kt < K; kt += 32) {
        #pragma unroll
        for (int p = 0; p < 4; p++) {
            int idx = t + 128*p;
            int r = idx >> 5, k = idx & 31;
            Ash[r][k] = Am[(size_t)(row0 + r) * K + kt + k];
        }
        #pragma unroll 8
        for (int kk = 0; kk < 32; kk++)
            Bsh[kk][t] = Bm[(size_t)(kt + kk) * 128 + t];
        __syncthreads();
        #pragma unroll
        for (int kk = 0; kk < 32; kk++) {
            float bv = Bsh[kk][t];
            #pragma unroll
            for (int r = 0; r < 16; r++) acc[r] += Ash[r][kk] * bv;
        }
        __syncthreads();
    }
    #pragma unroll
    for (int r = 0; r < 16; r++)
        Cm[(size_t)(row0 + r) * 128 + t] = acc[r];
}

// -------- fused filter-network + neighbor aggregation (v2) --------
// One block per atom, 256 threads, 2 CTAs/SM.
// SMEM (floats), total 28160 = 112640 B:
//  w2s:  [0,16384)        filt_w2[l]  row-major (w2s[k*128+f])
//  Hs:   [16384,24576)    H[k][n]     k-major rows of 64  (also reused as reduce scratch)
//  w1s:  [24576,27776)    filt_w1[l]  (w1s[g*128+k])
//  b1s:  [27776,27904)
//  b2s:  [27904,28032)
//  cms:  [28032,28096)
//  nbrs: [28096,28160)    (int)
#define FA_SMEM_FLOATS 28160

__global__ __launch_bounds__(256, 2)
void filter_agg_kernel(const float* __restrict__ w1, const float* __restrict__ b1,
                       const float* __restrict__ w2, const float* __restrict__ b2,
                       const int* __restrict__ nb, int l) {
    extern __shared__ float sm[];
    float* w2s = sm;
    float* Hs  = sm + 16384;
    float* w1s = sm + 24576;
    float* b1s = sm + 27776;
    float* b2s = sm + 27904;
    float* cms = sm + 28032;
    int*   nbrs = (int*)(sm + 28096);

    int t = threadIdx.x;
    int i = blockIdx.x;                 // atom (global)
    int bofs = (i >> 9) << 9;           // structure base

    // ---- stage 0: cooperative loads ----
    {
        const float4* w2g = (const float4*)(w2 + (size_t)l * 16384);
        float4* w2d = (float4*)w2s;
        #pragma unroll
        for (int p = 0; p < 16; p++) w2d[t + 256*p] = w2g[t + 256*p];
        const float* w1g = w1 + (size_t)l * 3200;
        for (int idx = t; idx < 3200; idx += 256) w1s[idx] = w1g[idx];
        if (t < 128) {
            b1s[t] = b1[l*128 + t];
            b2s[t] = b2[l*128 + t];
        }
        if (t < 64) {
            cms[t] = d_cm[i*64 + t];
            nbrs[t] = nb[i*64 + t];
        }
    }
    __syncthreads();

    // ---- stage A: H[k][n] = ssp(f_ij[n,:] @ w1[:,k] + b1[k]) ----
    // warp w handles k in [w*16, w*16+16); lane owns n = lane and n = lane+32.
    {
        int lane = t & 31;
        int w = t >> 5;
        int kb = w * 16;
        const float* fg = d_fij + (size_t)i * 1600;
        float f0[NG], f1[NG];
        #pragma unroll
        for (int g = 0; g < NG; g++) {
            f0[g] = fg[lane*NG + g];
            f1[g] = fg[(lane+32)*NG + g];
        }
        #pragma unroll 2
        for (int k = kb; k < kb + 16; k++) {
            float a0 = b1s[k], a1 = b1s[k];
            #pragma unroll
            for (int g = 0; g < NG; g++) {
                float wv = w1s[g*128 + k];    // warp-uniform broadcast
                a0 += f0[g] * wv;
                a1 += f1[g] * wv;
            }
            Hs[k*64 + lane]      = ssp(a0);
            Hs[k*64 + lane + 32] = ssp(a1);
        }
    }
    __syncthreads();

    // ---- stage B: W[n][f] = H[n,:] @ w2[:,f] + b2[f]; then masked y-weighted sum ----
    // Thread tile: 4 n  x  8 f.  fgrp = t&15 (f0 = 8*fgrp), ngrp = t>>4 (n0 = 4*ngrp).
    {
        int fgrp = t & 15;
        int ngrp = t >> 4;
        int f0 = fgrp * 8;
        int n0 = ngrp * 4;

        float acc[4][8];
        #pragma unroll
        for (int a = 0; a < 4; a++)
            #pragma unroll
            for (int q = 0; q < 8; q++) acc[a][q] = 0.f;

        #pragma unroll 2
        for (int k = 0; k < 128; k++) {
            float4 h  = *(const float4*)&Hs[k*64 + n0];
            float4 wa = *(const float4*)&w2s[k*128 + f0];
            float4 wb = *(const float4*)&w2s[k*128 + f0 + 4];
            float hv[4] = {h.x, h.y, h.z, h.w};
            float wv[8] = {wa.x, wa.y, wa.z, wa.w, wb.x, wb.y, wb.z, wb.w};
            #pragma unroll
            for (int a = 0; a < 4; a++)
                #pragma unroll
                for (int q = 0; q < 8; q++)
                    acc[a][q] += hv[a] * wv[q];
        }

        // per-thread partial aggregation over its 4 neighbors
        float part[8];
        #pragma unroll
        for (int q = 0; q < 8; q++) part[q] = 0.f;
        float b2v[8];
        #pragma unroll
        for (int q = 0; q < 8; q++) b2v[q] = b2s[f0 + q];
        #pragma unroll
        for (int a = 0; a < 4; a++) {
            int n = n0 + a;
            float c = cms[n];
            const float* yr = d_y + (size_t)(bofs + nbrs[n]) * 128 + f0;
            float4 y0 = *(const float4*)&yr[0];
            float4 y1 = *(const float4*)&yr[4];
            float yv[8] = {y0.x, y0.y, y0.z, y0.w, y1.x, y1.y, y1.z, y1.w};
            #pragma unroll
            for (int q = 0; q < 8; q++)
                part[q] += c * yv[q] * (acc[a][q] + b2v[q]);
        }

        // cross-ngrp reduction through smem (reuse Hs as scratch)
        __syncthreads();
        float* scratch = Hs;   // 16 groups x 128 f = 2048 floats
        *(float4*)&scratch[ngrp*128 + f0]     = make_float4(part[0], part[1], part[2], part[3]);
        *(float4*)&scratch[ngrp*128 + f0 + 4] = make_float4(part[4], part[5], part[6], part[7]);
        __syncthreads();
        if (t < 128) {
            float s = 0.f;
            #pragma unroll
            for (int j = 0; j < 16; j++) s += scratch[j*128 + t];
            d_agg[(size_t)i*128 + t] = s;
        }
    }
}

// -------- fused epilogue: v_rad = (agg@f2out + b)@dense + b; x += ssp(v_rad + v_ang) --------
__global__ __launch_bounds__(128)
void out_kernel(const float* __restrict__ f2w, const float* __restrict__ f2b,
                const float* __restrict__ dw, const float* __restrict__ db, int l) {
    __shared__ float aggs[128];
    __shared__ float ts[128];
    int t = threadIdx.x;
    int i = blockIdx.x;
    aggs[t] = d_agg[(size_t)i*128 + t];
    __syncthreads();
    const float* wA = f2w + (size_t)l * 16384;
    float acc = f2b[l*128 + t];
    #pragma unroll 4
    for (int k = 0; k < 128; k++) acc += aggs[k] * wA[k*128 + t];
    ts[t] = acc;
    __syncthreads();
    const float* wB = dw + (size_t)l * 16384;
    float acc2 = db[l*128 + t];
    #pragma unroll 4
    for (int k = 0; k < 128; k++) acc2 += ts[k] * wB[k*128 + t];
    float v = acc2 + d_vang[(size_t)l*BA*ND + (size_t)i*128 + t];
    d_x[(size_t)i*128 + t] += ssp(v);
}

__global__ void copy_out_kernel(float* __restrict__ out) {
    int idx = blockIdx.x * 256 + threadIdx.x;
    out[idx] = d_x[idx];
}

extern "C" void kernel_launch(void* const* d_in, const int* in_sizes, int n_in,
                              void* d_out, int out_size) {
    const int*   z      = (const int*)  d_in[0];
    const float* pos    = (const float*)d_in[1];
    const int*   nb     = (const int*)  d_in[2];
    const int*   nmask  = (const int*)  d_in[3];
    const float* Gi     = (const float*)d_in[4];
    const float* emb    = (const float*)d_in[5];
    const float* fw1    = (const float*)d_in[6];
    const float* fb1    = (const float*)d_in[7];
    const float* fw2    = (const float*)d_in[8];
    const float* fb2    = (const float*)d_in[9];
    const float* in2f   = (const float*)d_in[10];
    const float* f2o    = (const float*)d_in[11];
    const float* f2ob   = (const float*)d_in[12];
    const float* dw     = (const float*)d_in[13];
    const float* db     = (const float*)d_in[14];
    const float* angw   = (const float*)d_in[15];
    float* out = (float*)d_out;

    cudaFuncSetAttribute(filter_agg_kernel,
                         cudaFuncAttributeMaxDynamicSharedMemorySize,
                         FA_SMEM_FLOATS * 4);

    embed_kernel<<<BA, 128>>>(z, emb);
    dist_kernel<<<BA, NN>>>(pos, nb, nmask);

    // all angular projections up front (layer-independent input G_i)
    for (int l = 0; l < NL; l++)
        gemm16_kernel<<<BA/16, 128>>>(Gi, angw + (size_t)l*NGA*ND, NGA, 0, 1, l*BA*ND);

    for (int l = 0; l < NL; l++) {
        gemm16_kernel<<<BA/16, 128>>>(nullptr, in2f + (size_t)l*ND*NF, ND, 1, 0, 0);
        filter_agg_kernel<<<BA, 256, FA_SMEM_FLOATS*4>>>(fw1, fb1, fw2, fb2, nb, l);
        out_kernel<<<BA, 128>>>(f2o, f2ob, dw, db, l);
    }

    copy_out_kernel<<<BA*ND/256, 256>>>(out);
}

// round 7
// speedup vs baseline: 1.6938x; 1.2336x over previous
#include <cuda_runtime.h>
#include <cuda_bf16.h>
#include <math.h>
#include <stdint.h>

#define NB 8
#define NA 512
#define NN 64
#define ND 128
#define NF 128
#define NG 25
#define NL 3
#define NGA 512
#define BA (NB*NA)          // 4096
#define CUTOFF 5.0f
#define RSTART 1.2f
#define LN2F 0.6931471805599453f

// -------- device scratch --------
__device__ float d_x[BA*ND];
__device__ float d_y[BA*NF];
__device__ float d_agg[BA*NF];
__device__ float d_vang[NL*BA*ND];
__device__ float d_fij[BA*NN*NG];
__device__ float d_cm[BA*NN];
__device__ __nv_bfloat16 d_w2hi[NL*NF*NF];   // w2^T split-high  [l][f][k]
__device__ __nv_bfloat16 d_w2lo[NL*NF*NF];   // w2^T split-low   [l][f][k]

// fast shifted-softplus: max(x,0) + log(1+exp(-|x|)) - ln2
__device__ __forceinline__ float ssp(float v) {
    return fmaxf(v, 0.f) + __logf(1.f + __expf(-fabsf(v))) - LN2F;
}

__device__ __forceinline__ uint32_t smem_u32(const void* p) {
    uint32_t a;
    asm("{ .reg .u64 t; cvta.to.shared.u64 t, %1; cvt.u32.u64 %0, t; }" : "=r"(a) : "l"(p));
    return a;
}

// -------- embedding gather --------
__global__ void embed_kernel(const int* __restrict__ z, const float* __restrict__ emb) {
    int i = blockIdx.x, t = threadIdx.x;
    d_x[i*ND + t] = emb[z[i]*ND + t];
}

// -------- distances + gaussian smearing + cutoff*mask --------
__global__ void dist_kernel(const float* __restrict__ pos,
                            const int* __restrict__ nb,
                            const int* __restrict__ nmask) {
    int i = blockIdx.x;
    int n = threadIdx.x;
    int bofs = (i >> 9) << 9;
    float px = pos[i*3+0], py = pos[i*3+1], pz = pos[i*3+2];
    int j = nb[i*NN + n];
    int gj = bofs + j;
    float dx = pos[gj*3+0] - px;
    float dy = pos[gj*3+1] - py;
    float dz = pos[gj*3+2] - pz;
    float r = sqrtf(dx*dx + dy*dy + dz*dz + 1e-12f);
    float m = (float)nmask[i*NN + n];
    d_cm[i*NN + n] = (r <= CUTOFF) ? m : 0.f;
    const float width = (CUTOFF - RSTART) / (float)(NG - 1);
    const float coeff = -0.5f / (width * width);
    float* out = d_fij + (size_t)(i*NN + n) * NG;
    #pragma unroll
    for (int g = 0; g < NG; g++) {
        float d = r - (RSTART + width * (float)g);
        out[g] = __expf(coeff * d * d);
    }
}

// -------- prestage: transpose + bf16-split filt_w2 --------
__global__ void w2split_kernel(const float* __restrict__ w2) {
    int idx = blockIdx.x * 256 + threadIdx.x;       // over NL*128*128
    int l = idx >> 14;
    int r = idx & 16383;
    int k = r >> 7, f = r & 127;
    float v = w2[idx];
    __nv_bfloat16 hi = __float2bfloat16(v);
    __nv_bfloat16 lo = __float2bfloat16(v - __bfloat162float(hi));
    int o = l*16384 + f*128 + k;                    // transposed [f][k]
    d_w2hi[o] = hi;
    d_w2lo[o] = lo;
}

// -------- tiled GEMM: C[M,128] = A[M,K] @ B[K,128]; blockIdx.y = layer --------
__global__ __launch_bounds__(128)
void gemm16_kernel(const float* __restrict__ Aext, const float* __restrict__ Bm0,
                   int K, int amode, int cmode) {
    __shared__ float Ash[16][32];
    __shared__ float Bsh[32][128];
    int l = blockIdx.y;
    const float* Bm = Bm0 + (size_t)l * K * 128;
    const float* Am = (amode == 1) ? d_x : Aext;
    float* Cm = (cmode == 1) ? (d_vang + (size_t)l*BA*ND) : d_y;
    int t = threadIdx.x;
    int row0 = blockIdx.x * 16;
    float acc[16];
    #pragma unroll
    for (int r = 0; r < 16; r++) acc[r] = 0.f;
    for (int kt = 0; kt < K; kt += 32) {
        #pragma unroll
        for (int p = 0; p < 4; p++) {
            int idx = t + 128*p;
            int r = idx >> 5, k = idx & 31;
            Ash[r][k] = Am[(size_t)(row0 + r) * K + kt + k];
        }
        #pragma unroll 8
        for (int kk = 0; kk < 32; kk++)
            Bsh[kk][t] = Bm[(size_t)(kt + kk) * 128 + t];
        __syncthreads();
        #pragma unroll
        for (int kk = 0; kk < 32; kk++) {
            float bv = Bsh[kk][t];
            #pragma unroll
            for (int r = 0; r < 16; r++) acc[r] += Ash[r][kk] * bv;
        }
        __syncthreads();
    }
    #pragma unroll
    for (int r = 0; r < 16; r++)
        Cm[(size_t)(row0 + r) * 128 + t] = acc[r];
}

// -------- filter-network + aggregation via mma.sync bf16-split --------
// One CTA per 2 atoms, 256 threads.
// bf16 tiles padded to 136 elems/row (272 B) -> ldmatrix conflict-free.
// SMEM (bytes):
//  AHI [0,34816)  ALO [34816,69632)  BHI [69632,104448)  BLO [104448,139264)
//  W1  [139264,152064)  B1 [152064,152576)  B2 [152576,153088)
//  CM  [153088,153600)  NBS [153600,154112)
// After MMA, W fp32 [128][132] overlays AHI/ALO (67584 B <= 69632).
#define OFF_AHI 0
#define OFF_ALO 34816
#define OFF_BHI 69632
#define OFF_BLO 104448
#define OFF_W1  139264
#define OFF_B1  152064
#define OFF_B2  152576
#define OFF_CM  153088
#define OFF_NB  153600
#define FA_SMEM 154112
#define TSTRIDE 272   // bytes per bf16 tile row (136 elems)

__global__ __launch_bounds__(256, 1)
void filter_agg_kernel(const float* __restrict__ w1, const float* __restrict__ b1,
                       const float* __restrict__ b2,
                       const int* __restrict__ nbg, int l)
{
    extern __shared__ char smc[];
    uint32_t sb = smem_u32(smc);
    float* w1s = (float*)(smc + OFF_W1);
    float* b1s = (float*)(smc + OFF_B1);
    float* b2s = (float*)(smc + OFF_B2);
    float* cms = (float*)(smc + OFF_CM);
    int*   nbs = (int*)(smc + OFF_NB);

    int t = threadIdx.x;
    int lane = t & 31;
    int w = t >> 5;
    int i0 = blockIdx.x * 2;
    int bofs = (i0 >> 9) << 9;

    // ---- stage 0: load prestaged bf16 w2 tiles + w1/bias/mask ----
    {
        const uint4* hsrc = (const uint4*)(d_w2hi + (size_t)l * 16384);
        const uint4* lsrc = (const uint4*)(d_w2lo + (size_t)l * 16384);
        for (int u = t; u < 2048; u += 256) {       // row f = 16 uint4 (256 B)
            int f = u >> 4, c = u & 15;
            *(uint4*)(smc + OFF_BHI + f*TSTRIDE + c*16) = hsrc[u];
            *(uint4*)(smc + OFF_BLO + f*TSTRIDE + c*16) = lsrc[u];
        }
        const float* w1g = w1 + (size_t)l * 3200;
        for (int idx = t; idx < 3200; idx += 256) w1s[idx] = w1g[idx];
        if (t < 128) {
            b1s[t] = b1[l*128 + t];
            b2s[t] = b2[l*128 + t];
            cms[t] = d_cm[i0*64 + t];       // [0,64) atom0, [64,128) atom1
            nbs[t] = nbg[i0*64 + t];
        }
    }
    __syncthreads();

    // ---- stage A: H = ssp(f_ij @ w1 + b1); bf16 split into A tiles ----
    {
        int atom = w >> 2;
        int kb = (w & 3) * 32;
        const float* fg = d_fij + (size_t)(i0 + atom) * 1600;
        float fr0[NG], fr1[NG];
        #pragma unroll
        for (int g = 0; g < NG; g++) {
            fr0[g] = fg[lane*NG + g];
            fr1[g] = fg[(lane+32)*NG + g];
        }
        int r0 = atom*64 + lane, r1 = r0 + 32;
        for (int k = kb; k < kb + 32; k++) {
            float a0 = b1s[k], a1 = a0;
            #pragma unroll
            for (int g = 0; g < NG; g++) {
                float wv = w1s[g*128 + k];
                a0 = fmaf(fr0[g], wv, a0);
                a1 = fmaf(fr1[g], wv, a1);
            }
            float h0 = ssp(a0), h1 = ssp(a1);
            __nv_bfloat16 h0h = __float2bfloat16(h0);
            __nv_bfloat16 h0l = __float2bfloat16(h0 - __bfloat162float(h0h));
            __nv_bfloat16 h1h = __float2bfloat16(h1);
            __nv_bfloat16 h1l = __float2bfloat16(h1 - __bfloat162float(h1h));
            *(__nv_bfloat16*)(smc + OFF_AHI + r0*TSTRIDE + k*2) = h0h;
            *(__nv_bfloat16*)(smc + OFF_ALO + r0*TSTRIDE + k*2) = h0l;
            *(__nv_bfloat16*)(smc + OFF_AHI + r1*TSTRIDE + k*2) = h1h;
            *(__nv_bfloat16*)(smc + OFF_ALO + r1*TSTRIDE + k*2) = h1l;
        }
    }
    __syncthreads();

    // ---- stage B: D[128,128] = Ahi*Bhi^T + Ahi*Blo^T + Alo*Bhi^T via mma.sync ----
    // warp w owns rows [w*16, w*16+16). 16 n-tiles of 8 f, 8 k-steps of 16.
    float acc[16][4];
    {
        #pragma unroll
        for (int j = 0; j < 16; j++)
            #pragma unroll
            for (int q = 0; q < 4; q++) acc[j][q] = 0.f;

        int R0 = w * 16;
        // A ldmatrix address: row = R0 + (lane&15), k-halfsel byte ofs = (lane&16)
        uint32_t aHi = sb + OFF_AHI + (uint32_t)(R0 + (lane & 15)) * TSTRIDE + (uint32_t)(lane & 16);
        uint32_t aLo = aHi + (OFF_ALO - OFF_AHI);
        // B ldmatrix.x2 address: row f = 8j + (lane&7), k-halfsel = ((lane&8)>>3)*16
        uint32_t bRow = (uint32_t)(lane & 7) * TSTRIDE + (uint32_t)((lane & 8) << 1);
        uint32_t bHi = sb + OFF_BHI + bRow;
        uint32_t bLo = sb + OFF_BLO + bRow;

        for (int s = 0; s < 8; s++) {
            uint32_t ah[4], al[4];
            asm volatile("ldmatrix.sync.aligned.m8n8.x4.shared.b16 {%0,%1,%2,%3}, [%4];"
                         : "=r"(ah[0]),"=r"(ah[1]),"=r"(ah[2]),"=r"(ah[3]) : "r"(aHi + s*32));
            asm volatile("ldmatrix.sync.aligned.m8n8.x4.shared.b16 {%0,%1,%2,%3}, [%4];"
                         : "=r"(al[0]),"=r"(al[1]),"=r"(al[2]),"=r"(al[3]) : "r"(aLo + s*32));
            #pragma unroll
            for (int j = 0; j < 16; j++) {
                uint32_t bh[2], bl[2];
                uint32_t bo = j * (8*TSTRIDE) + s*32;
                asm volatile("ldmatrix.sync.aligned.m8n8.x2.shared.b16 {%0,%1}, [%2];"
                             : "=r"(bh[0]),"=r"(bh[1]) : "r"(bHi + bo));
                asm volatile("ldmatrix.sync.aligned.m8n8.x2.shared.b16 {%0,%1}, [%2];"
                             : "=r"(bl[0]),"=r"(bl[1]) : "r"(bLo + bo));
                asm volatile("mma.sync.aligned.m16n8k16.row.col.f32.bf16.bf16.f32 "
                             "{%0,%1,%2,%3}, {%4,%5,%6,%7}, {%8,%9}, {%0,%1,%2,%3};"
                             : "+f"(acc[j][0]),"+f"(acc[j][1]),"+f"(acc[j][2]),"+f"(acc[j][3])
                             : "r"(ah[0]),"r"(ah[1]),"r"(ah[2]),"r"(ah[3]), "r"(bh[0]),"r"(bh[1]));
                asm volatile("mma.sync.aligned.m16n8k16.row.col.f32.bf16.bf16.f32 "
                             "{%0,%1,%2,%3}, {%4,%5,%6,%7}, {%8,%9}, {%0,%1,%2,%3};"
                             : "+f"(acc[j][0]),"+f"(acc[j][1]),"+f"(acc[j][2]),"+f"(acc[j][3])
                             : "r"(ah[0]),"r"(ah[1]),"r"(ah[2]),"r"(ah[3]), "r"(bl[0]),"r"(bl[1]));
                asm volatile("mma.sync.aligned.m16n8k16.row.col.f32.bf16.bf16.f32 "
                             "{%0,%1,%2,%3}, {%4,%5,%6,%7}, {%8,%9}, {%0,%1,%2,%3};"
                             : "+f"(acc[j][0]),"+f"(acc[j][1]),"+f"(acc[j][2]),"+f"(acc[j][3])
                             : "r"(al[0]),"r"(al[1]),"r"(al[2]),"r"(al[3]), "r"(bh[0]),"r"(bh[1]));
            }
        }
    }
    __syncthreads();   // A tiles dead; overlay W fp32 [128][132]

    // ---- write fragments to W ----
    {
        float* Wsh = (float*)(smc + OFF_AHI);
        int g = lane >> 2, tig = lane & 3;
        int r = w*16 + g;
        #pragma unroll
        for (int j = 0; j < 16; j++) {
            int f0 = j*8 + 2*tig;
            Wsh[r*132 + f0]       = acc[j][0];
            Wsh[r*132 + f0 + 1]   = acc[j][1];
            Wsh[(r+8)*132 + f0]   = acc[j][2];
            Wsh[(r+8)*132 + f0+1] = acc[j][3];
        }
    }
    __syncthreads();

    // ---- aggregation: agg[f] = sum_n cm[n] * y[nbr[n]][f] * (W[n][f] + b2[f]) ----
    {
        const float* Wsh = (const float*)(smc + OFF_AHI);
        int a = t >> 7, f = t & 127;
        float b2f = b2s[f];
        const float* cma = cms + a*64;
        const int*   nba = nbs + a*64;
        float s = 0.f;
        #pragma unroll 4
        for (int n = 0; n < 64; n++) {
            float c = cma[n];
            float yv = d_y[(size_t)(bofs + nba[n])*128 + f];
            s = fmaf(c * yv, Wsh[(a*64 + n)*132 + f] + b2f, s);
        }
        d_agg[(size_t)(i0 + a)*128 + f] = s;
    }
}

// -------- fused epilogue --------
__global__ __launch_bounds__(128)
void out_kernel(const float* __restrict__ f2w, const float* __restrict__ f2b,
                const float* __restrict__ dw, const float* __restrict__ db, int l) {
    __shared__ float aggs[128];
    __shared__ float ts[128];
    int t = threadIdx.x;
    int i = blockIdx.x;
    aggs[t] = d_agg[(size_t)i*128 + t];
    __syncthreads();
    const float* wA = f2w + (size_t)l * 16384;
    float acc = f2b[l*128 + t];
    #pragma unroll 4
    for (int k = 0; k < 128; k++) acc += aggs[k] * wA[k*128 + t];
    ts[t] = acc;
    __syncthreads();
    const float* wB = dw + (size_t)l * 16384;
    float acc2 = db[l*128 + t];
    #pragma unroll 4
    for (int k = 0; k < 128; k++) acc2 += ts[k] * wB[k*128 + t];
    float v = acc2 + d_vang[(size_t)l*BA*ND + (size_t)i*128 + t];
    d_x[(size_t)i*128 + t] += ssp(v);
}

__global__ void copy_out_kernel(float* __restrict__ out) {
    int idx = blockIdx.x * 256 + threadIdx.x;
    out[idx] = d_x[idx];
}

extern "C" void kernel_launch(void* const* d_in, const int* in_sizes, int n_in,
                              void* d_out, int out_size) {
    const int*   z      = (const int*)  d_in[0];
    const float* pos    = (const float*)d_in[1];
    const int*   nb     = (const int*)  d_in[2];
    const int*   nmask  = (const int*)  d_in[3];
    const float* Gi     = (const float*)d_in[4];
    const float* emb    = (const float*)d_in[5];
    const float* fw1    = (const float*)d_in[6];
    const float* fb1    = (const float*)d_in[7];
    const float* fw2    = (const float*)d_in[8];
    const float* fb2    = (const float*)d_in[9];
    const float* in2f   = (const float*)d_in[10];
    const float* f2o    = (const float*)d_in[11];
    const float* f2ob   = (const float*)d_in[12];
    const float* dw     = (const float*)d_in[13];
    const float* db     = (const float*)d_in[14];
    const float* angw   = (const float*)d_in[15];
    float* out = (float*)d_out;

    cudaFuncSetAttribute(filter_agg_kernel,
                         cudaFuncAttributeMaxDynamicSharedMemorySize, FA_SMEM);

    embed_kernel<<<BA, 128>>>(z, emb);
    dist_kernel<<<BA, NN>>>(pos, nb, nmask);
    w2split_kernel<<<NL*64, 256>>>(fw2);

    // all 3 angular projections in one launch
    gemm16_kernel<<<dim3(BA/16, NL), 128>>>(Gi, angw, NGA, 0, 1);

    for (int l = 0; l < NL; l++) {
        gemm16_kernel<<<dim3(BA/16, 1), 128>>>(nullptr, in2f + (size_t)l*ND*NF, ND, 1, 0);
        filter_agg_kernel<<<BA/2, 256, FA_SMEM>>>(fw1, fb1, fb2, nb, l);
        out_kernel<<<BA, 128>>>(f2o, f2ob, dw, db, l);
    }

    copy_out_kernel<<<BA*ND/256, 256>>>(out);
}

// round 8
// speedup vs baseline: 2.7545x; 1.6262x over previous
#include <cuda_runtime.h>
#include <cuda_bf16.h>
#include <math.h>
#include <stdint.h>

#define NB 8
#define NA 512
#define NN 64
#define ND 128
#define NF 128
#define NG 25
#define NL 3
#define NGA 512
#define BA (NB*NA)          // 4096
#define CUTOFF 5.0f
#define RSTART 1.2f
#define LN2F 0.6931471805599453f

// -------- device scratch --------
__device__ float d_x[BA*ND];
__device__ float d_y[BA*NF];
__device__ float d_agg[BA*NF];
__device__ float d_vang[NL*BA*ND];
__device__ float d_fij[BA*NN*NG];
__device__ float d_cm[BA*NN];
__device__ __nv_bfloat16 d_w2hi[NL*NF*NF];   // w2^T split-high  [l][f][k]
__device__ __nv_bfloat16 d_w2lo[NL*NF*NF];   // w2^T split-low   [l][f][k]

__device__ __forceinline__ float ssp(float v) {
    return fmaxf(v, 0.f) + __logf(1.f + __expf(-fabsf(v))) - LN2F;
}

__device__ __forceinline__ uint32_t smem_u32(const void* p) {
    uint32_t a;
    asm("{ .reg .u64 t; cvta.to.shared.u64 t, %1; cvt.u32.u64 %0, t; }" : "=r"(a) : "l"(p));
    return a;
}

// split two floats into packed bf16x2 hi and lo parts (lo = residual)
__device__ __forceinline__ void split2(float a, float b, uint32_t& hi, uint32_t& lo) {
    __nv_bfloat16 ah = __float2bfloat16(a), bh = __float2bfloat16(b);
    float ar = a - __bfloat162float(ah);
    float br = b - __bfloat162float(bh);
    __nv_bfloat162 hp; hp.x = ah; hp.y = bh;
    __nv_bfloat162 lp = __floats2bfloat162_rn(ar, br);
    hi = *(uint32_t*)&hp;
    lo = *(uint32_t*)&lp;
}

// -------- embedding gather --------
__global__ void embed_kernel(const int* __restrict__ z, const float* __restrict__ emb) {
    int i = blockIdx.x, t = threadIdx.x;
    d_x[i*ND + t] = emb[z[i]*ND + t];
}

// -------- distances + gaussian smearing + cutoff*mask --------
__global__ void dist_kernel(const float* __restrict__ pos,
                            const int* __restrict__ nb,
                            const int* __restrict__ nmask) {
    int i = blockIdx.x;
    int n = threadIdx.x;
    int bofs = (i >> 9) << 9;
    float px = pos[i*3+0], py = pos[i*3+1], pz = pos[i*3+2];
    int j = nb[i*NN + n];
    int gj = bofs + j;
    float dx = pos[gj*3+0] - px;
    float dy = pos[gj*3+1] - py;
    float dz = pos[gj*3+2] - pz;
    float r = sqrtf(dx*dx + dy*dy + dz*dz + 1e-12f);
    float m = (float)nmask[i*NN + n];
    d_cm[i*NN + n] = (r <= CUTOFF) ? m : 0.f;
    const float width = (CUTOFF - RSTART) / (float)(NG - 1);
    const float coeff = -0.5f / (width * width);
    float* out = d_fij + (size_t)(i*NN + n) * NG;
    #pragma unroll
    for (int g = 0; g < NG; g++) {
        float d = r - (RSTART + width * (float)g);
        out[g] = __expf(coeff * d * d);
    }
}

// -------- prestage: transpose + bf16-split filt_w2 --------
__global__ void w2split_kernel(const float* __restrict__ w2) {
    int idx = blockIdx.x * 256 + threadIdx.x;       // over NL*128*128
    int l = idx >> 14;
    int r = idx & 16383;
    int k = r >> 7, f = r & 127;
    float v = w2[idx];
    __nv_bfloat16 hi = __float2bfloat16(v);
    __nv_bfloat16 lo = __float2bfloat16(v - __bfloat162float(hi));
    int o = l*16384 + f*128 + k;                    // transposed [f][k]
    d_w2hi[o] = hi;
    d_w2lo[o] = lo;
}

// -------- tiled GEMM: C[M,128] = A[M,K] @ B[K,128]; blockIdx.y = layer --------
__global__ __launch_bounds__(128)
void gemm16_kernel(const float* __restrict__ Aext, const float* __restrict__ Bm0,
                   int K, int amode, int cmode) {
    __shared__ float Ash[16][32];
    __shared__ float Bsh[32][128];
    int l = blockIdx.y;
    const float* Bm = Bm0 + (size_t)l * K * 128;
    const float* Am = (amode == 1) ? d_x : Aext;
    float* Cm = (cmode == 1) ? (d_vang + (size_t)l*BA*ND) : d_y;
    int t = threadIdx.x;
    int row0 = blockIdx.x * 16;
    float acc[16];
    #pragma unroll
    for (int r = 0; r < 16; r++) acc[r] = 0.f;
    for (int kt = 0; kt < K; kt += 32) {
        #pragma unroll
        for (int p = 0; p < 4; p++) {
            int idx = t + 128*p;
            int r = idx >> 5, k = idx & 31;
            Ash[r][k] = Am[(size_t)(row0 + r) * K + kt + k];
        }
        #pragma unroll 8
        for (int kk = 0; kk < 32; kk++)
            Bsh[kk][t] = Bm[(size_t)(kt + kk) * 128 + t];
        __syncthreads();
        #pragma unroll
        for (int kk = 0; kk < 32; kk++) {
            float bv = Bsh[kk][t];
            #pragma unroll
            for (int r = 0; r < 16; r++) acc[r] += Ash[r][kk] * bv;
        }
        __syncthreads();
    }
    #pragma unroll
    for (int r = 0; r < 16; r++)
        Cm[(size_t)(row0 + r) * 128 + t] = acc[r];
}

// -------- filter-network + aggregation, fragment-direct (v3) --------
// One CTA per 2 atoms, 256 threads, 2 CTAs/SM.
// A fragments computed in registers (no smem staging); aggregation fused
// into accumulator fragments (no W smem). Only B tiles + w1 + small live in smem.
#define TSTRIDE 272    // bytes per B bf16 row (136 elems, conflict-free ldmatrix)
#define OFF_BHI 0
#define OFF_BLO 34816
#define OFF_W1  69632
#define OFF_B1  82432
#define OFF_B2  82944
#define OFF_CM  83456
#define OFF_NB  83968
#define OFF_RED 84480
#define FA_SMEM 88576

__global__ __launch_bounds__(256, 2)
void filter_agg_kernel(const float* __restrict__ w1, const float* __restrict__ b1,
                       const float* __restrict__ b2,
                       const int* __restrict__ nbg, int l)
{
    extern __shared__ char smc[];
    uint32_t sb = smem_u32(smc);
    float* w1s = (float*)(smc + OFF_W1);
    float* b1s = (float*)(smc + OFF_B1);
    float* b2s = (float*)(smc + OFF_B2);
    float* cms = (float*)(smc + OFF_CM);
    int*   nbs = (int*)(smc + OFF_NB);
    float* red = (float*)(smc + OFF_RED);

    int t = threadIdx.x;
    int lane = t & 31;
    int w = t >> 5;
    int g = lane >> 2;      // fragment row group
    int tt = lane & 3;      // fragment col group
    int atom = w >> 2;      // warps 0-3 -> atom 0 (rows 0-63), 4-7 -> atom 1
    int i0 = blockIdx.x * 2;
    int bofs = (i0 >> 9) << 9;

    // ---- stage 0: cooperative loads ----
    {
        const uint4* hsrc = (const uint4*)(d_w2hi + (size_t)l * 16384);
        const uint4* lsrc = (const uint4*)(d_w2lo + (size_t)l * 16384);
        for (int u = t; u < 2048; u += 256) {
            int f = u >> 4, c = u & 15;
            *(uint4*)(smc + OFF_BHI + f*TSTRIDE + c*16) = hsrc[u];
            *(uint4*)(smc + OFF_BLO + f*TSTRIDE + c*16) = lsrc[u];
        }
        const float* w1g = w1 + (size_t)l * 3200;
        for (int idx = t; idx < 3200; idx += 256) w1s[idx] = w1g[idx];
        if (t < 128) {
            b1s[t] = b1[l*128 + t];
            b2s[t] = b2[l*128 + t];
            cms[t] = d_cm[i0*64 + t];
            nbs[t] = nbg[i0*64 + t];
        }
    }
    __syncthreads();

    // ---- stage A: compute A fragments in registers ----
    // thread rows (local within pair): row0p = atom*64 + (w&3)*16 + g, row1p = row0p + 8
    int row0p = atom*64 + (w & 3)*16 + g;
    int row1p = row0p + 8;
    uint32_t ahi[32], alo[32];     // [s][q]: q0=(r0,klo) q1=(r1,klo) q2=(r0,khi) q3=(r1,khi)
    {
        const float* fg = d_fij + (size_t)i0 * 1600;   // pair base; row*25 within
        #pragma unroll
        for (int phase = 0; phase < 2; phase++) {
            int rl = (phase == 0) ? row0p : row1p;
            float fij[NG];
            #pragma unroll
            for (int q = 0; q < NG; q++) fij[q] = fg[rl*NG + q];
            #pragma unroll
            for (int s = 0; s < 8; s++) {
                int k0 = s*16 + 2*tt;
                float A0 = b1s[k0], A1 = b1s[k0+1];
                float A2 = b1s[k0+8], A3 = b1s[k0+9];
                #pragma unroll
                for (int q = 0; q < NG; q++) {
                    float2 wlo = *(const float2*)&w1s[q*128 + k0];
                    float2 whi = *(const float2*)&w1s[q*128 + k0 + 8];
                    A0 = fmaf(fij[q], wlo.x, A0);
                    A1 = fmaf(fij[q], wlo.y, A1);
                    A2 = fmaf(fij[q], whi.x, A2);
                    A3 = fmaf(fij[q], whi.y, A3);
                }
                float h0 = ssp(A0), h1 = ssp(A1), h2 = ssp(A2), h3 = ssp(A3);
                uint32_t hA, lA, hB, lB;
                split2(h0, h1, hA, lA);
                split2(h2, h3, hB, lB);
                if (phase == 0) {
                    ahi[s*4+0] = hA; alo[s*4+0] = lA;
                    ahi[s*4+2] = hB; alo[s*4+2] = lB;
                } else {
                    ahi[s*4+1] = hA; alo[s*4+1] = lA;
                    ahi[s*4+3] = hB; alo[s*4+3] = lB;
                }
            }
        }
    }

    // ---- stage B: mma + fused aggregation fold ----
    float cm0 = cms[row0p], cm1 = cms[row1p];
    const float* yp0 = d_y + (size_t)(bofs + nbs[row0p]) * 128;
    const float* yp1 = d_y + (size_t)(bofs + nbs[row1p]) * 128;
    uint32_t bBase = sb + OFF_BHI + (uint32_t)(lane & 7)*TSTRIDE + (uint32_t)((lane & 8) << 1);

    float part[32];
    #pragma unroll
    for (int q = 0; q < 32; q++) part[q] = 0.f;

    #pragma unroll
    for (int j = 0; j < 16; j++) {
        float c0 = 0.f, c1 = 0.f, c2 = 0.f, c3 = 0.f;
        #pragma unroll
        for (int s = 0; s < 8; s++) {
            uint32_t ba = bBase + (uint32_t)(j * (8*TSTRIDE) + s*32);
            uint32_t bh0, bh1, bl0, bl1;
            asm volatile("ldmatrix.sync.aligned.m8n8.x2.shared.b16 {%0,%1}, [%2];"
                         : "=r"(bh0), "=r"(bh1) : "r"(ba));
            asm volatile("ldmatrix.sync.aligned.m8n8.x2.shared.b16 {%0,%1}, [%2];"
                         : "=r"(bl0), "=r"(bl1) : "r"(ba + (OFF_BLO - OFF_BHI)));
            asm volatile("mma.sync.aligned.m16n8k16.row.col.f32.bf16.bf16.f32 "
                         "{%0,%1,%2,%3}, {%4,%5,%6,%7}, {%8,%9}, {%0,%1,%2,%3};"
                         : "+f"(c0), "+f"(c1), "+f"(c2), "+f"(c3)
                         : "r"(ahi[s*4+0]), "r"(ahi[s*4+1]), "r"(ahi[s*4+2]), "r"(ahi[s*4+3]),
                           "r"(bh0), "r"(bh1));
            asm volatile("mma.sync.aligned.m16n8k16.row.col.f32.bf16.bf16.f32 "
                         "{%0,%1,%2,%3}, {%4,%5,%6,%7}, {%8,%9}, {%0,%1,%2,%3};"
                         : "+f"(c0), "+f"(c1), "+f"(c2), "+f"(c3)
                         : "r"(ahi[s*4+0]), "r"(ahi[s*4+1]), "r"(ahi[s*4+2]), "r"(ahi[s*4+3]),
                           "r"(bl0), "r"(bl1));
            asm volatile("mma.sync.aligned.m16n8k16.row.col.f32.bf16.bf16.f32 "
                         "{%0,%1,%2,%3}, {%4,%5,%6,%7}, {%8,%9}, {%0,%1,%2,%3};"
                         : "+f"(c0), "+f"(c1), "+f"(c2), "+f"(c3)
                         : "r"(alo[s*4+0]), "r"(alo[s*4+1]), "r"(alo[s*4+2]), "r"(alo[s*4+3]),
                           "r"(bh0), "r"(bh1));
        }
        // fold: c0,c1 = row0p, f = 8j+2tt, +1 ; c2,c3 = row1p
        int fa = 8*j + 2*tt;
        float2 b2v = *(const float2*)&b2s[fa];
        float2 ya  = *(const float2*)(yp0 + fa);
        float2 yb  = *(const float2*)(yp1 + fa);
        part[2*j]   += cm0*ya.x*(c0 + b2v.x) + cm1*yb.x*(c2 + b2v.x);
        part[2*j+1] += cm0*ya.y*(c1 + b2v.y) + cm1*yb.y*(c3 + b2v.y);
    }

    // ---- cross-row-group reduction (lane bits 2..4), then cross-warp ----
    #pragma unroll
    for (int q = 0; q < 32; q++) {
        part[q] += __shfl_xor_sync(0xffffffffu, part[q], 4);
        part[q] += __shfl_xor_sync(0xffffffffu, part[q], 8);
        part[q] += __shfl_xor_sync(0xffffffffu, part[q], 16);
    }
    if (lane < 4) {
        #pragma unroll
        for (int j = 0; j < 16; j++)
            *(float2*)&red[w*128 + 8*j + 2*tt] = make_float2(part[2*j], part[2*j+1]);
    }
    __syncthreads();
    {
        int a = t >> 7, f = t & 127;
        const float* rb = red + (a*4)*128 + f;
        d_agg[(size_t)(i0 + a)*128 + f] = rb[0] + rb[128] + rb[256] + rb[384];
    }
}

// -------- fused epilogue --------
__global__ __launch_bounds__(128)
void out_kernel(const float* __restrict__ f2w, const float* __restrict__ f2b,
                const float* __restrict__ dw, const float* __restrict__ db, int l) {
    __shared__ float aggs[128];
    __shared__ float ts[128];
    int t = threadIdx.x;
    int i = blockIdx.x;
    aggs[t] = d_agg[(size_t)i*128 + t];
    __syncthreads();
    const float* wA = f2w + (size_t)l * 16384;
    float acc = f2b[l*128 + t];
    #pragma unroll 4
    for (int k = 0; k < 128; k++) acc += aggs[k] * wA[k*128 + t];
    ts[t] = acc;
    __syncthreads();
    const float* wB = dw + (size_t)l * 16384;
    float acc2 = db[l*128 + t];
    #pragma unroll 4
    for (int k = 0; k < 128; k++) acc2 += ts[k] * wB[k*128 + t];
    float v = acc2 + d_vang[(size_t)l*BA*ND + (size_t)i*128 + t];
    d_x[(size_t)i*128 + t] += ssp(v);
}

__global__ void copy_out_kernel(float* __restrict__ out) {
    int idx = blockIdx.x * 256 + threadIdx.x;
    out[idx] = d_x[idx];
}

extern "C" void kernel_launch(void* const* d_in, const int* in_sizes, int n_in,
                              void* d_out, int out_size) {
    const int*   z      = (const int*)  d_in[0];
    const float* pos    = (const float*)d_in[1];
    const int*   nb     = (const int*)  d_in[2];
    const int*   nmask  = (const int*)  d_in[3];
    const float* Gi     = (const float*)d_in[4];
    const float* emb    = (const float*)d_in[5];
    const float* fw1    = (const float*)d_in[6];
    const float* fb1    = (const float*)d_in[7];
    const float* fw2    = (const float*)d_in[8];
    const float* fb2    = (const float*)d_in[9];
    const float* in2f   = (const float*)d_in[10];
    const float* f2o    = (const float*)d_in[11];
    const float* f2ob   = (const float*)d_in[12];
    const float* dw     = (const float*)d_in[13];
    const float* db     = (const float*)d_in[14];
    const float* angw   = (const float*)d_in[15];
    float* out = (float*)d_out;

    cudaFuncSetAttribute(filter_agg_kernel,
                         cudaFuncAttributeMaxDynamicSharedMemorySize, FA_SMEM);

    embed_kernel<<<BA, 128>>>(z, emb);
    dist_kernel<<<BA, NN>>>(pos, nb, nmask);
    w2split_kernel<<<NL*64, 256>>>(fw2);

    gemm16_kernel<<<dim3(BA/16, NL), 128>>>(Gi, angw, NGA, 0, 1);

    for (int l = 0; l < NL; l++) {
        gemm16_kernel<<<dim3(BA/16, 1), 128>>>(nullptr, in2f + (size_t)l*ND*NF, ND, 1, 0);
        filter_agg_kernel<<<BA/2, 256, FA_SMEM>>>(fw1, fb1, fb2, nb, l);
        out_kernel<<<BA, 128>>>(f2o, f2ob, dw, db, l);
    }

    copy_out_kernel<<<BA*ND/256, 256>>>(out);
}

// round 11
// speedup vs baseline: 3.1847x; 1.1562x over previous
#include <cuda_runtime.h>
#include <cuda_bf16.h>
#include <math.h>
#include <stdint.h>

#define NB 8
#define NA 512
#define NN 64
#define ND 128
#define NF 128
#define NG 25
#define NL 3
#define NGA 512
#define BA (NB*NA)          // 4096
#define CUTOFF 5.0f
#define RSTART 1.2f
#define LN2F 0.6931471805599453f

// -------- device scratch --------
__device__ float d_x[BA*ND];
__device__ float d_y[BA*NF];
__device__ float d_agg[BA*NF];
__device__ float d_vang[NL*BA*ND];
__device__ float d_fij[BA*NN*NG];
__device__ float d_cm[BA*NN];
__device__ __nv_bfloat16 d_w2hi[NL*NF*NF];      // w2^T split  [l][f][k]
__device__ __nv_bfloat16 d_w2lo[NL*NF*NF];
__device__ __nv_bfloat16 d_i2fhi[NL*NF*ND];     // in2f^T split [l][f][k]
__device__ __nv_bfloat16 d_i2flo[NL*NF*ND];
__device__ __nv_bfloat16 d_anghi[NL*ND*NGA];    // angw^T split [l][f][k]
__device__ __nv_bfloat16 d_anglo[NL*ND*NGA];
__device__ float d_wc[NL*ND*ND];                // f2w @ dense composite
__device__ float d_bc[NL*ND];                   // f2b @ dense + db

__device__ __forceinline__ float ssp(float v) {
    return fmaxf(v, 0.f) + __logf(1.f + __expf(-fabsf(v))) - LN2F;
}

__device__ __forceinline__ uint32_t smem_u32(const void* p) {
    uint32_t a;
    asm("{ .reg .u64 t; cvta.to.shared.u64 t, %1; cvt.u32.u64 %0, t; }" : "=r"(a) : "l"(p));
    return a;
}

__device__ __forceinline__ void split2(float a, float b, uint32_t& hi, uint32_t& lo) {
    __nv_bfloat16 ah = __float2bfloat16(a), bh = __float2bfloat16(b);
    float ar = a - __bfloat162float(ah);
    float br = b - __bfloat162float(bh);
    __nv_bfloat162 hp; hp.x = ah; hp.y = bh;
    __nv_bfloat162 lp = __floats2bfloat162_rn(ar, br);
    hi = *(uint32_t*)&hp;
    lo = *(uint32_t*)&lp;
}

// -------- embedding gather --------
__global__ void embed_kernel(const int* __restrict__ z, const float* __restrict__ emb) {
    int i = blockIdx.x, t = threadIdx.x;
    d_x[i*ND + t] = emb[z[i]*ND + t];
}

// -------- distances + gaussian smearing + cutoff*mask --------
__global__ void dist_kernel(const float* __restrict__ pos,
                            const int* __restrict__ nb,
                            const int* __restrict__ nmask) {
    int i = blockIdx.x;
    int n = threadIdx.x;
    int bofs = (i >> 9) << 9;
    float px = pos[i*3+0], py = pos[i*3+1], pz = pos[i*3+2];
    int j = nb[i*NN + n];
    int gj = bofs + j;
    float dx = pos[gj*3+0] - px;
    float dy = pos[gj*3+1] - py;
    float dz = pos[gj*3+2] - pz;
    float r = sqrtf(dx*dx + dy*dy + dz*dz + 1e-12f);
    float m = (float)nmask[i*NN + n];
    d_cm[i*NN + n] = (r <= CUTOFF) ? m : 0.f;
    const float width = (CUTOFF - RSTART) / (float)(NG - 1);
    const float coeff = -0.5f / (width * width);
    float* out = d_fij + (size_t)(i*NN + n) * NG;
    #pragma unroll
    for (int g = 0; g < NG; g++) {
        float d = r - (RSTART + width * (float)g);
        out[g] = __expf(coeff * d * d);
    }
}

// -------- prestage: transpose + bf16-split a [NL][K][128] weight to [l][f][K] --------
__global__ void bsplit_kernel(const float* __restrict__ src,
                              __nv_bfloat16* __restrict__ dhi,
                              __nv_bfloat16* __restrict__ dlo, int K) {
    int idx = blockIdx.x * 256 + threadIdx.x;     // over NL*K*128
    int l = idx / (K*128);
    int r = idx % (K*128);
    int k = r >> 7, f = r & 127;
    float v = src[idx];
    __nv_bfloat16 hi = __float2bfloat16(v);
    __nv_bfloat16 lo = __float2bfloat16(v - __bfloat162float(hi));
    int o = l*K*128 + f*K + k;
    dhi[o] = hi;
    dlo[o] = lo;
}

// -------- prestage: composite epilogue weights --------
__global__ __launch_bounds__(128)
void wc_kernel(const float* __restrict__ f2w, const float* __restrict__ dwm) {
    __shared__ float Ash[16][32];
    __shared__ float Bsh[32][128];
    int l = blockIdx.y;
    const float* Am = f2w + (size_t)l*16384;
    const float* Bm = dwm + (size_t)l*16384;
    float* Cm = d_wc + (size_t)l*16384;
    int t = threadIdx.x;
    int row0 = blockIdx.x * 16;
    float acc[16];
    #pragma unroll
    for (int r = 0; r < 16; r++) acc[r] = 0.f;
    for (int kt = 0; kt < 128; kt += 32) {
        #pragma unroll
        for (int p = 0; p < 4; p++) {
            int idx = t + 128*p;
            Ash[idx >> 5][idx & 31] = Am[(row0 + (idx >> 5))*128 + kt + (idx & 31)];
        }
        #pragma unroll 8
        for (int kk = 0; kk < 32; kk++) Bsh[kk][t] = Bm[(kt + kk)*128 + t];
        __syncthreads();
        #pragma unroll
        for (int kk = 0; kk < 32; kk++) {
            float bv = Bsh[kk][t];
            #pragma unroll
            for (int r = 0; r < 16; r++) acc[r] += Ash[r][kk] * bv;
        }
        __syncthreads();
    }
    #pragma unroll
    for (int r = 0; r < 16; r++) Cm[(row0 + r)*128 + t] = acc[r];
}

__global__ void bc_kernel(const float* __restrict__ f2b, const float* __restrict__ dwm,
                          const float* __restrict__ db) {
    int l = blockIdx.x, t = threadIdx.x;
    float acc = db[l*128 + t];
    #pragma unroll 4
    for (int k = 0; k < 128; k++)
        acc += f2b[l*128 + k] * dwm[(size_t)l*16384 + k*128 + t];
    d_bc[l*128 + t] = acc;
}

// -------- tensor GEMM: C[M,128] = A[M,K] @ B[K,128], bf16 hi/lo split --------
// M-tile 64, 256 threads (8 warps: w>>1 = 16-row block, w&1 = f half of 64).
// A fp32 split on the fly; B prestaged transposed-split [l][f][K].
// smem: AHI [64][72]b16 9216B, ALO 9216, BHI [128][72] 18432, BLO 18432 = 55296 B.
#define TG_AHI 0
#define TG_ALO 9216
#define TG_BHI 18432
#define TG_BLO 36864
#define TG_SMEM 55296
#define TG_STRIDE 144

__global__ __launch_bounds__(256, 2)
void tgemm_kernel(const float* __restrict__ Aext,
                  const __nv_bfloat16* __restrict__ BtHi,
                  const __nv_bfloat16* __restrict__ BtLo,
                  int K, int amode, int cmode) {
    extern __shared__ char smc[];
    uint32_t sb = smem_u32(smc);
    int t = threadIdx.x;
    int lane = t & 31;
    int w = t >> 5;
    int l = blockIdx.y;
    int M0 = blockIdx.x * 64;
    const float* Ap = (amode == 1) ? d_x : Aext;
    float* Cp = (cmode == 1) ? (d_vang + (size_t)l*BA*ND) : d_y;
    const __nv_bfloat16* bhiL = BtHi + (size_t)l*128*K;
    const __nv_bfloat16* bloL = BtLo + (size_t)l*128*K;

    int R0 = (w >> 1) * 16;
    int jbase = (w & 1) * 8;

    float acc[8][4];
    #pragma unroll
    for (int j = 0; j < 8; j++)
        #pragma unroll
        for (int q = 0; q < 4; q++) acc[j][q] = 0.f;

    uint32_t aAddr = sb + TG_AHI + (uint32_t)(R0 + (lane & 15))*TG_STRIDE + (uint32_t)(lane & 16);
    uint32_t bAddr = sb + TG_BHI + (uint32_t)(lane & 7)*TG_STRIDE + (uint32_t)((lane & 8) << 1);

    for (int kc = 0; kc < K; kc += 64) {
        // load + split A chunk [64][64]
        #pragma unroll
        for (int p = 0; p < 8; p++) {
            int u = t + 256*p;              // 2048 float2 slots
            int r = u >> 5, kp = u & 31;
            float2 v = *(const float2*)&Ap[(size_t)(M0 + r)*K + kc + kp*2];
            uint32_t hi, lo;
            split2(v.x, v.y, hi, lo);
            *(uint32_t*)(smc + TG_AHI + r*TG_STRIDE + kp*4) = hi;
            *(uint32_t*)(smc + TG_ALO + r*TG_STRIDE + kp*4) = lo;
        }
        // copy B chunk [128][64]
        #pragma unroll
        for (int p = 0; p < 4; p++) {
            int u = t + 256*p;              // 1024 uint4 slots
            int f = u >> 3, c = u & 7;
            *(uint4*)(smc + TG_BHI + f*TG_STRIDE + c*16) =
                ((const uint4*)(bhiL + f*K + kc))[c];
            *(uint4*)(smc + TG_BLO + f*TG_STRIDE + c*16) =
                ((const uint4*)(bloL + f*K + kc))[c];
        }
        __syncthreads();

        #pragma unroll
        for (int s = 0; s < 4; s++) {
            uint32_t ah[4], al[4];
            asm volatile("ldmatrix.sync.aligned.m8n8.x4.shared.b16 {%0,%1,%2,%3}, [%4];"
                         : "=r"(ah[0]),"=r"(ah[1]),"=r"(ah[2]),"=r"(ah[3])
                         : "r"(aAddr + s*32));
            asm volatile("ldmatrix.sync.aligned.m8n8.x4.shared.b16 {%0,%1,%2,%3}, [%4];"
                         : "=r"(al[0]),"=r"(al[1]),"=r"(al[2]),"=r"(al[3])
                         : "r"(aAddr + (TG_ALO - TG_AHI) + s*32));
            #pragma unroll
            for (int j = 0; j < 8; j++) {
                uint32_t ba = bAddr + (uint32_t)((jbase + j)*(8*TG_STRIDE) + s*32);
                uint32_t bh0, bh1, bl0, bl1;
                asm volatile("ldmatrix.sync.aligned.m8n8.x2.shared.b16 {%0,%1}, [%2];"
                             : "=r"(bh0), "=r"(bh1) : "r"(ba));
                asm volatile("ldmatrix.sync.aligned.m8n8.x2.shared.b16 {%0,%1}, [%2];"
                             : "=r"(bl0), "=r"(bl1) : "r"(ba + (TG_BLO - TG_BHI)));
                asm volatile("mma.sync.aligned.m16n8k16.row.col.f32.bf16.bf16.f32 "
                             "{%0,%1,%2,%3}, {%4,%5,%6,%7}, {%8,%9}, {%0,%1,%2,%3};"
                             : "+f"(acc[j][0]),"+f"(acc[j][1]),"+f"(acc[j][2]),"+f"(acc[j][3])
                             : "r"(ah[0]),"r"(ah[1]),"r"(ah[2]),"r"(ah[3]),"r"(bh0),"r"(bh1));
                asm volatile("mma.sync.aligned.m16n8k16.row.col.f32.bf16.bf16.f32 "
                             "{%0,%1,%2,%3}, {%4,%5,%6,%7}, {%8,%9}, {%0,%1,%2,%3};"
                             : "+f"(acc[j][0]),"+f"(acc[j][1]),"+f"(acc[j][2]),"+f"(acc[j][3])
                             : "r"(ah[0]),"r"(ah[1]),"r"(ah[2]),"r"(ah[3]),"r"(bl0),"r"(bl1));
                asm volatile("mma.sync.aligned.m16n8k16.row.col.f32.bf16.bf16.f32 "
                             "{%0,%1,%2,%3}, {%4,%5,%6,%7}, {%8,%9}, {%0,%1,%2,%3};"
                             : "+f"(acc[j][0]),"+f"(acc[j][1]),"+f"(acc[j][2]),"+f"(acc[j][3])
                             : "r"(al[0]),"r"(al[1]),"r"(al[2]),"r"(al[3]),"r"(bh0),"r"(bh1));
            }
        }
        __syncthreads();
    }

    // write C fragments
    {
        int g = lane >> 2, tt = lane & 3;
        int r0 = M0 + R0 + g;
        #pragma unroll
        for (int j = 0; j < 8; j++) {
            int fa = (jbase + j)*8 + 2*tt;
            *(float2*)&Cp[(size_t)r0*128 + fa]     = make_float2(acc[j][0], acc[j][1]);
            *(float2*)&Cp[(size_t)(r0+8)*128 + fa] = make_float2(acc[j][2], acc[j][3]);
        }
    }
}

// -------- filter-network + aggregation, fragment-direct (unchanged from R7) --------
#define TSTRIDE 272
#define OFF_BHI 0
#define OFF_BLO 34816
#define OFF_W1  69632
#define OFF_B1  82432
#define OFF_B2  82944
#define OFF_CM  83456
#define OFF_NB  83968
#define OFF_RED 84480
#define FA_SMEM 88576

__global__ __launch_bounds__(256, 2)
void filter_agg_kernel(const float* __restrict__ w1, const float* __restrict__ b1,
                       const float* __restrict__ b2,
                       const int* __restrict__ nbg, int l)
{
    extern __shared__ char smc[];
    uint32_t sb = smem_u32(smc);
    float* w1s = (float*)(smc + OFF_W1);
    float* b1s = (float*)(smc + OFF_B1);
    float* b2s = (float*)(smc + OFF_B2);
    float* cms = (float*)(smc + OFF_CM);
    int*   nbs = (int*)(smc + OFF_NB);
    float* red = (float*)(smc + OFF_RED);

    int t = threadIdx.x;
    int lane = t & 31;
    int w = t >> 5;
    int g = lane >> 2;
    int tt = lane & 3;
    int atom = w >> 2;
    int i0 = blockIdx.x * 2;
    int bofs = (i0 >> 9) << 9;

    {
        const uint4* hsrc = (const uint4*)(d_w2hi + (size_t)l * 16384);
        const uint4* lsrc = (const uint4*)(d_w2lo + (size_t)l * 16384);
        for (int u = t; u < 2048; u += 256) {
            int f = u >> 4, c = u & 15;
            *(uint4*)(smc + OFF_BHI + f*TSTRIDE + c*16) = hsrc[u];
            *(uint4*)(smc + OFF_BLO + f*TSTRIDE + c*16) = lsrc[u];
        }
        const float* w1g = w1 + (size_t)l * 3200;
        for (int idx = t; idx < 3200; idx += 256) w1s[idx] = w1g[idx];
        if (t < 128) {
            b1s[t] = b1[l*128 + t];
            b2s[t] = b2[l*128 + t];
            cms[t] = d_cm[i0*64 + t];
            nbs[t] = nbg[i0*64 + t];
        }
    }
    __syncthreads();

    int row0p = atom*64 + (w & 3)*16 + g;
    int row1p = row0p + 8;
    uint32_t ahi[32], alo[32];
    {
        const float* fg = d_fij + (size_t)i0 * 1600;
        #pragma unroll
        for (int phase = 0; phase < 2; phase++) {
            int rl = (phase == 0) ? row0p : row1p;
            float fij[NG];
            #pragma unroll
            for (int q = 0; q < NG; q++) fij[q] = fg[rl*NG + q];
            #pragma unroll
            for (int s = 0; s < 8; s++) {
                int k0 = s*16 + 2*tt;
                float A0 = b1s[k0], A1 = b1s[k0+1];
                float A2 = b1s[k0+8], A3 = b1s[k0+9];
                #pragma unroll
                for (int q = 0; q < NG; q++) {
                    float2 wlo = *(const float2*)&w1s[q*128 + k0];
                    float2 whi = *(const float2*)&w1s[q*128 + k0 + 8];
                    A0 = fmaf(fij[q], wlo.x, A0);
                    A1 = fmaf(fij[q], wlo.y, A1);
                    A2 = fmaf(fij[q], whi.x, A2);
                    A3 = fmaf(fij[q], whi.y, A3);
                }
                float h0 = ssp(A0), h1 = ssp(A1), h2 = ssp(A2), h3 = ssp(A3);
                uint32_t hA, lA, hB, lB;
                split2(h0, h1, hA, lA);
                split2(h2, h3, hB, lB);
                if (phase == 0) {
                    ahi[s*4+0] = hA; alo[s*4+0] = lA;
                    ahi[s*4+2] = hB; alo[s*4+2] = lB;
                } else {
                    ahi[s*4+1] = hA; alo[s*4+1] = lA;
                    ahi[s*4+3] = hB; alo[s*4+3] = lB;
                }
            }
        }
    }

    float cm0 = cms[row0p], cm1 = cms[row1p];
    const float* yp0 = d_y + (size_t)(bofs + nbs[row0p]) * 128;
    const float* yp1 = d_y + (size_t)(bofs + nbs[row1p]) * 128;
    uint32_t bBase = sb + OFF_BHI + (uint32_t)(lane & 7)*TSTRIDE + (uint32_t)((lane & 8) << 1);

    float part[32];
    #pragma unroll
    for (int q = 0; q < 32; q++) part[q] = 0.f;

    #pragma unroll
    for (int j = 0; j < 16; j++) {
        float c0 = 0.f, c1 = 0.f, c2 = 0.f, c3 = 0.f;
        #pragma unroll
        for (int s = 0; s < 8; s++) {
            uint32_t ba = bBase + (uint32_t)(j * (8*TSTRIDE) + s*32);
            uint32_t bh0, bh1, bl0, bl1;
            asm volatile("ldmatrix.sync.aligned.m8n8.x2.shared.b16 {%0,%1}, [%2];"
                         : "=r"(bh0), "=r"(bh1) : "r"(ba));
            asm volatile("ldmatrix.sync.aligned.m8n8.x2.shared.b16 {%0,%1}, [%2];"
                         : "=r"(bl0), "=r"(bl1) : "r"(ba + (OFF_BLO - OFF_BHI)));
            asm volatile("mma.sync.aligned.m16n8k16.row.col.f32.bf16.bf16.f32 "
                         "{%0,%1,%2,%3}, {%4,%5,%6,%7}, {%8,%9}, {%0,%1,%2,%3};"
                         : "+f"(c0), "+f"(c1), "+f"(c2), "+f"(c3)
                         : "r"(ahi[s*4+0]), "r"(ahi[s*4+1]), "r"(ahi[s*4+2]), "r"(ahi[s*4+3]),
                           "r"(bh0), "r"(bh1));
            asm volatile("mma.sync.aligned.m16n8k16.row.col.f32.bf16.bf16.f32 "
                         "{%0,%1,%2,%3}, {%4,%5,%6,%7}, {%8,%9}, {%0,%1,%2,%3};"
                         : "+f"(c0), "+f"(c1), "+f"(c2), "+f"(c3)
                         : "r"(ahi[s*4+0]), "r"(ahi[s*4+1]), "r"(ahi[s*4+2]), "r"(ahi[s*4+3]),
                           "r"(bl0), "r"(bl1));
            asm volatile("mma.sync.aligned.m16n8k16.row.col.f32.bf16.bf16.f32 "
                         "{%0,%1,%2,%3}, {%4,%5,%6,%7}, {%8,%9}, {%0,%1,%2,%3};"
                         : "+f"(c0), "+f"(c1), "+f"(c2), "+f"(c3)
                         : "r"(alo[s*4+0]), "r"(alo[s*4+1]), "r"(alo[s*4+2]), "r"(alo[s*4+3]),
                           "r"(bh0), "r"(bh1));
        }
        int fa = 8*j + 2*tt;
        float2 b2v = *(const float2*)&b2s[fa];
        float2 ya  = *(const float2*)(yp0 + fa);
        float2 yb  = *(const float2*)(yp1 + fa);
        part[2*j]   += cm0*ya.x*(c0 + b2v.x) + cm1*yb.x*(c2 + b2v.x);
        part[2*j+1] += cm0*ya.y*(c1 + b2v.y) + cm1*yb.y*(c3 + b2v.y);
    }

    #pragma unroll
    for (int q = 0; q < 32; q++) {
        part[q] += __shfl_xor_sync(0xffffffffu, part[q], 4);
        part[q] += __shfl_xor_sync(0xffffffffu, part[q], 8);
        part[q] += __shfl_xor_sync(0xffffffffu, part[q], 16);
    }
    if (lane < 4) {
        #pragma unroll
        for (int j = 0; j < 16; j++)
            *(float2*)&red[w*128 + 8*j + 2*tt] = make_float2(part[2*j], part[2*j+1]);
    }
    __syncthreads();
    {
        int a = t >> 7, f = t & 127;
        const float* rb = red + (a*4)*128 + f;
        d_agg[(size_t)(i0 + a)*128 + f] = rb[0] + rb[128] + rb[256] + rb[384];
    }
}

// -------- fused epilogue (composite weights): x += ssp(agg@Wc + bc + vang) --------
__global__ __launch_bounds__(128)
void out_kernel(int l) {
    __shared__ float aggs[128];
    int t = threadIdx.x;
    int i = blockIdx.x;
    aggs[t] = d_agg[(size_t)i*128 + t];
    __syncthreads();
    const float* wC = d_wc + (size_t)l * 16384;
    float acc = d_bc[l*128 + t];
    #pragma unroll 4
    for (int k = 0; k < 128; k++) acc += aggs[k] * wC[k*128 + t];
    float v = acc + d_vang[(size_t)l*BA*ND + (size_t)i*128 + t];
    d_x[(size_t)i*128 + t] += ssp(v);
}

__global__ void w2split_kernel(const float* __restrict__ w2) {
    int idx = blockIdx.x * 256 + threadIdx.x;
    int l = idx >> 14;
    int r = idx & 16383;
    int k = r >> 7, f = r & 127;
    float v = w2[idx];
    __nv_bfloat16 hi = __float2bfloat16(v);
    __nv_bfloat16 lo = __float2bfloat16(v - __bfloat162float(hi));
    int o = l*16384 + f*128 + k;
    d_w2hi[o] = hi;
    d_w2lo[o] = lo;
}

__global__ void copy_out_kernel(float* __restrict__ out) {
    int idx = blockIdx.x * 256 + threadIdx.x;
    out[idx] = d_x[idx];
}

extern "C" void kernel_launch(void* const* d_in, const int* in_sizes, int n_in,
                              void* d_out, int out_size) {
    const int*   z      = (const int*)  d_in[0];
    const float* pos    = (const float*)d_in[1];
    const int*   nb     = (const int*)  d_in[2];
    const int*   nmask  = (const int*)  d_in[3];
    const float* Gi     = (const float*)d_in[4];
    const float* emb    = (const float*)d_in[5];
    const float* fw1    = (const float*)d_in[6];
    const float* fb1    = (const float*)d_in[7];
    const float* fw2    = (const float*)d_in[8];
    const float* fb2    = (const float*)d_in[9];
    const float* in2f   = (const float*)d_in[10];
    const float* f2o    = (const float*)d_in[11];
    const float* f2ob   = (const float*)d_in[12];
    const float* dw     = (const float*)d_in[13];
    const float* db     = (const float*)d_in[14];
    const float* angw   = (const float*)d_in[15];
    float* out = (float*)d_out;

    static __nv_bfloat16 *p_i2fhi, *p_i2flo, *p_anghi, *p_anglo;
    cudaGetSymbolAddress((void**)&p_i2fhi, d_i2fhi);
    cudaGetSymbolAddress((void**)&p_i2flo, d_i2flo);
    cudaGetSymbolAddress((void**)&p_anghi, d_anghi);
    cudaGetSymbolAddress((void**)&p_anglo, d_anglo);

    cudaFuncSetAttribute(filter_agg_kernel,
                         cudaFuncAttributeMaxDynamicSharedMemorySize, FA_SMEM);
    cudaFuncSetAttribute(tgemm_kernel,
                         cudaFuncAttributeMaxDynamicSharedMemorySize, TG_SMEM);

    // prep (all layer-invariant)
    embed_kernel<<<BA, 128>>>(z, emb);
    dist_kernel<<<BA, NN>>>(pos, nb, nmask);
    w2split_kernel<<<NL*64, 256>>>(fw2);
    bsplit_kernel<<<NL*ND*NF/256, 256>>>(in2f, p_i2fhi, p_i2flo, ND);
    bsplit_kernel<<<NL*NGA*ND/256, 256>>>(angw, p_anghi, p_anglo, NGA);
    wc_kernel<<<dim3(8, NL), 128>>>(f2o, dw);
    bc_kernel<<<NL, 128>>>(f2ob, dw, db);

    // all 3 angular projections via tensor cores
    tgemm_kernel<<<dim3(BA/64, NL), 256, TG_SMEM>>>(Gi, p_anghi, p_anglo, NGA, 0, 1);

    for (int l = 0; l < NL; l++) {
        tgemm_kernel<<<dim3(BA/64, 1), 256, TG_SMEM>>>(nullptr,
            p_i2fhi + (size_t)l*NF*ND, p_i2flo + (size_t)l*NF*ND, ND, 1, 0);
        filter_agg_kernel<<<BA/2, 256, FA_SMEM>>>(fw1, fb1, fb2, nb, l);
        out_kernel<<<BA, 128>>>(l);
    }

    copy_out_kernel<<<BA*ND/256, 256>>>(out);
}